// round 2
// baseline (speedup 1.0000x reference)
#include <cuda_runtime.h>
#include <cstdint>

#define N_NODES 50000
#define DIM 128

// Scratch (static device globals — no allocation at runtime)
__device__ float g_agg[(size_t)N_NODES * DIM];   // weighted neighbor sums
__device__ float g_deg[N_NODES];                 // in-degree
__device__ float g_h1[(size_t)N_NODES * DIM];    // hidden activations after layer 1

// ---------------------------------------------------------------------------
// zero: grid-stride float4 clear
// ---------------------------------------------------------------------------
__global__ void zero_kernel(float4* __restrict__ p, int n4) {
    int i = blockIdx.x * blockDim.x + threadIdx.x;
    float4 z = make_float4(0.f, 0.f, 0.f, 0.f);
    for (; i < n4; i += gridDim.x * blockDim.x) p[i] = z;
}

// ---------------------------------------------------------------------------
// edge scatter: one warp per edge.
//   lane l handles dims [4l, 4l+4):  agg[dst] += w * h[src]   (vector red)
// ---------------------------------------------------------------------------
__global__ void edge_kernel(const float* __restrict__ h,
                            const int*   __restrict__ src,
                            const int*   __restrict__ dst,
                            const float* __restrict__ wt,
                            float*       __restrict__ agg,
                            float*       __restrict__ deg,
                            int E, int update_deg)
{
    int warp = (blockIdx.x * blockDim.x + threadIdx.x) >> 5;
    int lane = threadIdx.x & 31;
    if (warp >= E) return;

    int s = src[warp];
    int d = dst[warp];
    float w = wt[warp];

    const float4* hv = (const float4*)(h + (size_t)s * DIM);
    float4 v = hv[lane];
    v.x *= w; v.y *= w; v.z *= w; v.w *= w;

    float* ap = agg + (size_t)d * DIM + lane * 4;
    asm volatile("red.global.add.v4.f32 [%0], {%1, %2, %3, %4};"
                 :: "l"(ap), "f"(v.x), "f"(v.y), "f"(v.z), "f"(v.w)
                 : "memory");

    if (update_deg && lane == 0)
        atomicAdd(deg + d, 1.0f);
}

// ---------------------------------------------------------------------------
// Fused SAGE GEMM, v2: 128x128 CTA tile, 256 threads, 8x8 thread tile.
//   out[r, j] = sum_k h[r,k]*Ws[j,k] + (agg[r,k]/max(deg[r],1))*Wn[j,k] + b[j]
// K = 256 (self half then neighbor half), chunked by KC=32.
// Per kk step per thread: 8 broadcast scalar LDS (a) + 2 LDS.128 (w) feed
// 64 FFMA -> 86% FFMA instruction mix.
// ---------------------------------------------------------------------------
#define TILE_ROWS 128
#define KC 32

__global__ __launch_bounds__(256, 2)
void sage_gemm(const float* __restrict__ Aself,
               const float* __restrict__ Aneigh,
               const float* __restrict__ deg,
               const float* __restrict__ Ws,
               const float* __restrict__ Wn,
               const float* __restrict__ bias,
               float*       __restrict__ out,
               int nrows, int do_relu)
{
    __shared__ float As[TILE_ROWS][KC + 4];   // stride 36: f4-aligned rows; a-reads are 2-addr broadcast
    __shared__ float Wt[KC][DIM + 4];         // stride 132: f4-aligned rows; w-reads contiguous conflict-free
    __shared__ float rdeg_s[TILE_ROWS];
    __shared__ float bs[DIM];

    int tid = threadIdx.x;
    int tx = tid & 15;        // output-column group: cols [8*tx, 8*tx+8)
    int ty = tid >> 4;        // output-row group:    rows [8*ty, 8*ty+8)
    int rowbase = blockIdx.x * TILE_ROWS;

    if (tid < TILE_ROWS) {
        int r = rowbase + tid;
        float dg = (r < nrows) ? deg[r] : 1.0f;
        rdeg_s[tid] = 1.0f / fmaxf(dg, 1.0f);
    }
    if (tid < DIM) bs[tid] = bias[tid];

    float acc[8][8];
#pragma unroll
    for (int i = 0; i < 8; i++)
#pragma unroll
        for (int m = 0; m < 8; m++) acc[i][m] = 0.f;

    for (int kc = 0; kc < 2 * DIM; kc += KC) {
        __syncthreads();

        // ---- load W chunk (transposed): Wt[kk][j] = W[j][kb+kk] ----
        {
            const float* W = (kc < DIM) ? Ws : Wn;
            int kb = kc & (DIM - 1);
#pragma unroll
            for (int it = 0; it < (KC * DIM) / 256; it++) {
                int idx = tid + it * 256;       // 0..4095
                int kk = idx & (KC - 1);
                int j  = idx >> 5;
                Wt[kk][j] = W[j * DIM + kb + kk];   // coalesced global read
            }
        }

        // ---- load A chunk (self half, or deg-scaled neighbor half) ----
        // 128 rows x 32 floats = 1024 float4; 256 threads x 4 quads.
        {
#pragma unroll
            for (int it = 0; it < 4; it++) {
                int q = tid + it * 256;         // 0..1023
                int lrow = q >> 3;              // 0..127
                int lcol = (q & 7) * 4;         // 0..28
                int grow = rowbase + lrow;
                if (grow > nrows - 1) grow = nrows - 1;   // clamp (discarded on store)
                float4 v;
                if (kc < DIM) {
                    v = *(const float4*)(Aself + (size_t)grow * DIM + kc + lcol);
                } else {
                    v = *(const float4*)(Aneigh + (size_t)grow * DIM + (kc - DIM) + lcol);
                    float rd = rdeg_s[lrow];
                    v.x *= rd; v.y *= rd; v.z *= rd; v.w *= rd;
                }
                *(float4*)&As[lrow][lcol] = v;
            }
        }
        __syncthreads();

        // ---- inner product: 64 FFMA per kk per thread ----
#pragma unroll
        for (int kk = 0; kk < KC; kk++) {
            float a[8], w[8];
            float4 w0 = *(const float4*)&Wt[kk][tx * 8];
            float4 w1 = *(const float4*)&Wt[kk][tx * 8 + 4];
            w[0] = w0.x; w[1] = w0.y; w[2] = w0.z; w[3] = w0.w;
            w[4] = w1.x; w[5] = w1.y; w[6] = w1.z; w[7] = w1.w;
#pragma unroll
            for (int i = 0; i < 8; i++) a[i] = As[ty * 8 + i][kk];
#pragma unroll
            for (int i = 0; i < 8; i++)
#pragma unroll
                for (int m = 0; m < 8; m++)
                    acc[i][m] += a[i] * w[m];
        }
    }

    // ---- epilogue: bias (+ relu), float4 stores, coalesced across tx ----
#pragma unroll
    for (int i = 0; i < 8; i++) {
        int r = rowbase + ty * 8 + i;
        if (r < nrows) {
            float o[8];
#pragma unroll
            for (int m = 0; m < 8; m++) {
                float v = acc[i][m] + bs[tx * 8 + m];
                o[m] = do_relu ? fmaxf(v, 0.f) : v;
            }
            float* op = out + (size_t)r * DIM + tx * 8;
            *(float4*)(op)     = make_float4(o[0], o[1], o[2], o[3]);
            *(float4*)(op + 4) = make_float4(o[4], o[5], o[6], o[7]);
        }
    }
}

// ---------------------------------------------------------------------------
extern "C" void kernel_launch(void* const* d_in, const int* in_sizes, int n_in,
                              void* d_out, int out_size)
{
    const float* x   = (const float*)d_in[0];
    const int*   src = (const int*)  d_in[1];
    const int*   dst = (const int*)  d_in[2];
    const float* wt  = (const float*)d_in[3];
    const float* Ws1 = (const float*)d_in[4];
    const float* Wn1 = (const float*)d_in[5];
    const float* b1  = (const float*)d_in[6];
    const float* Ws2 = (const float*)d_in[7];
    const float* Wn2 = (const float*)d_in[8];
    const float* b2  = (const float*)d_in[9];
    float* out = (float*)d_out;

    int E = in_sizes[1];

    float *agg, *deg, *h1;
    cudaGetSymbolAddress((void**)&agg, g_agg);
    cudaGetSymbolAddress((void**)&deg, g_deg);
    cudaGetSymbolAddress((void**)&h1,  g_h1);

    const int AGG4 = (N_NODES * DIM) / 4;
    const int DEG4 = N_NODES / 4;
    int eblocks = (E + 7) / 8;                 // 8 warps / block, 1 warp / edge
    int gblocks = (N_NODES + TILE_ROWS - 1) / TILE_ROWS;

    // ---- layer 1 ----
    zero_kernel<<<1024, 256>>>((float4*)agg, AGG4);
    zero_kernel<<<64,   256>>>((float4*)deg, DEG4);
    edge_kernel<<<eblocks, 256>>>(x, src, dst, wt, agg, deg, E, 1);
    sage_gemm<<<gblocks, 256>>>(x, agg, deg, Ws1, Wn1, b1, h1, N_NODES, 1);

    // ---- layer 2 (deg unchanged: same dst) ----
    zero_kernel<<<1024, 256>>>((float4*)agg, AGG4);
    edge_kernel<<<eblocks, 256>>>(h1, src, dst, wt, agg, deg, E, 0);
    sage_gemm<<<gblocks, 256>>>(h1, agg, deg, Ws2, Wn2, b2, out, N_NODES, 0);
}

// round 3
// speedup vs baseline: 1.0629x; 1.0629x over previous
#include <cuda_runtime.h>
#include <cstdint>

#define N_NODES 50000
#define E_MAX   625000
#define DIM     128

// ---------------------------------------------------------------------------
// Static device scratch (no runtime allocation)
// ---------------------------------------------------------------------------
__device__ int   g_cnt[N_NODES];                   // in-degree histogram
__device__ int   g_row[N_NODES + 1];               // CSR row offsets (by dst)
__device__ int   g_cur[N_NODES];                   // scatter cursors
__device__ int   g_esrc[E_MAX];                    // CSR-reordered src ids
__device__ float g_ew[E_MAX];                      // CSR-reordered edge weights
__device__ float g_h1[(size_t)N_NODES * DIM];      // layer-1 activations
__device__ float g_hn[(size_t)N_NODES * DIM];      // neighbor means (h_neigh)

// ---------------------------------------------------------------------------
// zero: grid-stride 16B clear (works for int or float payload)
// ---------------------------------------------------------------------------
__global__ void zero_kernel(float4* __restrict__ p, int n4) {
    int i = blockIdx.x * blockDim.x + threadIdx.x;
    float4 z = make_float4(0.f, 0.f, 0.f, 0.f);
    for (; i < n4; i += gridDim.x * blockDim.x) p[i] = z;
}

// ---------------------------------------------------------------------------
// CSR build, step 1: histogram of dst
// ---------------------------------------------------------------------------
__global__ void hist_kernel(const int* __restrict__ dst, int* __restrict__ cnt, int E) {
    int i = blockIdx.x * blockDim.x + threadIdx.x;
    for (; i < E; i += gridDim.x * blockDim.x)
        atomicAdd(&cnt[dst[i]], 1);
}

// ---------------------------------------------------------------------------
// CSR build, step 2: exclusive scan over cnt (single CTA, 1024 threads).
// Each thread owns a contiguous chunk; Hillis-Steele over the 1024 partials.
// Writes row offsets AND initializes scatter cursors.
// ---------------------------------------------------------------------------
#define SCAN_T 1024
__global__ void scan_kernel(const int* __restrict__ cnt,
                            int* __restrict__ row,
                            int* __restrict__ cur)
{
    __shared__ int partial[SCAN_T];
    const int CHUNK = (N_NODES + SCAN_T - 1) / SCAN_T;
    int t = threadIdx.x;
    int beg = t * CHUNK;
    int end = min(beg + CHUNK, N_NODES);

    int s = 0;
    for (int i = beg; i < end; i++) s += cnt[i];
    partial[t] = s;
    __syncthreads();

    for (int off = 1; off < SCAN_T; off <<= 1) {
        int v = 0;
        if (t >= off) v = partial[t - off];
        __syncthreads();
        if (t >= off) partial[t] += v;
        __syncthreads();
    }

    int run = (t == 0) ? 0 : partial[t - 1];
    for (int i = beg; i < end; i++) {
        row[i] = run;
        cur[i] = run;
        run += cnt[i];
    }
    if (t == SCAN_T - 1) row[N_NODES] = partial[SCAN_T - 1];
}

// ---------------------------------------------------------------------------
// CSR build, step 3: scatter edges into CSR slots (src + weight reordered)
// ---------------------------------------------------------------------------
__global__ void scatter_kernel(const int*   __restrict__ src,
                               const int*   __restrict__ dst,
                               const float* __restrict__ wt,
                               int*   __restrict__ cur,
                               int*   __restrict__ esrc,
                               float* __restrict__ ew,
                               int E)
{
    int i = blockIdx.x * blockDim.x + threadIdx.x;
    for (; i < E; i += gridDim.x * blockDim.x) {
        int p = atomicAdd(&cur[dst[i]], 1);
        esrc[p] = src[i];
        ew[p]   = wt[i];
    }
}

// ---------------------------------------------------------------------------
// Aggregation as a gather: one warp per destination node.
//   hn[n] = (1/max(deg,1)) * sum_e w_e * h[src_e]
// lane l owns dims [4l, 4l+4). Unrolled by 2 for MLP.
// ---------------------------------------------------------------------------
__global__ void gather_kernel(const float* __restrict__ h,
                              const int*   __restrict__ row,
                              const int*   __restrict__ esrc,
                              const float* __restrict__ ew,
                              float*       __restrict__ hn)
{
    int warp = (blockIdx.x * blockDim.x + threadIdx.x) >> 5;
    int lane = threadIdx.x & 31;
    if (warp >= N_NODES) return;

    int rs = row[warp];
    int re = row[warp + 1];

    float4 acc = make_float4(0.f, 0.f, 0.f, 0.f);
    int e = rs;
    for (; e + 1 < re; e += 2) {
        int   s0 = __ldg(&esrc[e]);
        int   s1 = __ldg(&esrc[e + 1]);
        float w0 = __ldg(&ew[e]);
        float w1 = __ldg(&ew[e + 1]);
        float4 v0 = *(const float4*)(h + (size_t)s0 * DIM + lane * 4);
        float4 v1 = *(const float4*)(h + (size_t)s1 * DIM + lane * 4);
        acc.x += w0 * v0.x + w1 * v1.x;
        acc.y += w0 * v0.y + w1 * v1.y;
        acc.z += w0 * v0.z + w1 * v1.z;
        acc.w += w0 * v0.w + w1 * v1.w;
    }
    if (e < re) {
        int   s0 = __ldg(&esrc[e]);
        float w0 = __ldg(&ew[e]);
        float4 v0 = *(const float4*)(h + (size_t)s0 * DIM + lane * 4);
        acc.x += w0 * v0.x; acc.y += w0 * v0.y;
        acc.z += w0 * v0.z; acc.w += w0 * v0.w;
    }

    float inv = 1.0f / fmaxf((float)(re - rs), 1.0f);
    acc.x *= inv; acc.y *= inv; acc.z *= inv; acc.w *= inv;
    *(float4*)(hn + (size_t)warp * DIM + lane * 4) = acc;
}

// ---------------------------------------------------------------------------
// Fused SAGE GEMM v3: 64x128 CTA tile, 128 threads, 8x8 thread tile.
//   out[r, j] = sum_k h[r,k]*Ws[j,k] + hn[r,k]*Wn[j,k] + b[j]
// K = 256 (self half then neighbor half), KC = 32.
// A tile stored TRANSPOSED: As_t[kk][row], row-stride 68 (16B-aligned,
// bank-offset 4) -> a-fragment = 2 broadcast LDS.128 per kk.
// Per kk per thread: 4 LDS.128 + 64 FFMA (94% FFMA mix).
// ---------------------------------------------------------------------------
#define TILE_ROWS 64
#define KC 32
#define AST_STRIDE 68   // 68*4B = 272B: float4-aligned, bank shift 4 per kk

__global__ __launch_bounds__(128, 3)
void sage_gemm(const float* __restrict__ Aself,
               const float* __restrict__ Aneigh,   // already deg-scaled
               const float* __restrict__ Ws,
               const float* __restrict__ Wn,
               const float* __restrict__ bias,
               float*       __restrict__ out,
               int nrows, int do_relu)
{
    __shared__ float As_t[KC][AST_STRIDE];    // [kk][row]
    __shared__ float Wt[KC][DIM + 4];         // [kk][j], stride 132 (16B-aligned)
    __shared__ float bs[DIM];

    int tid = threadIdx.x;
    int tx = tid & 15;        // column group: cols [8*tx, 8*tx+8)
    int ty = tid >> 4;        // row group:    rows [8*ty, 8*ty+8)
    int rowbase = blockIdx.x * TILE_ROWS;

    if (tid < DIM) bs[tid] = bias[tid];

    float acc[8][8];
#pragma unroll
    for (int i = 0; i < 8; i++)
#pragma unroll
        for (int m = 0; m < 8; m++) acc[i][m] = 0.f;

    for (int kc = 0; kc < 2 * DIM; kc += KC) {
        __syncthreads();

        // ---- W chunk (transposed): Wt[kk][j] = W[j][kb+kk] ----
        {
            const float* W = (kc < DIM) ? Ws : Wn;
            int kb = kc & (DIM - 1);
#pragma unroll
            for (int it = 0; it < (KC * DIM) / 128; it++) {
                int idx = tid + it * 128;       // 0..4095
                int kk = idx & (KC - 1);
                int j  = idx >> 5;
                Wt[kk][j] = W[j * DIM + kb + kk];   // coalesced 128B per warp
            }
        }

        // ---- A chunk, transposed into As_t[kk][row] ----
        // 64 rows x 32 k = 512 float4 loads; 128 threads x 4.
        {
            const float* A = (kc < DIM) ? Aself : Aneigh;
            int kb = kc & (DIM - 1);
#pragma unroll
            for (int it = 0; it < 4; it++) {
                int q = tid + it * 128;         // 0..511
                int lrow = q >> 3;              // 0..63
                int lk   = (q & 7) * 4;         // 0,4,...,28
                int grow = rowbase + lrow;
                if (grow > nrows - 1) grow = nrows - 1;   // clamp (discarded on store)
                float4 v = *(const float4*)(A + (size_t)grow * DIM + kb + lk);
                As_t[lk + 0][lrow] = v.x;
                As_t[lk + 1][lrow] = v.y;
                As_t[lk + 2][lrow] = v.z;
                As_t[lk + 3][lrow] = v.w;
            }
        }
        __syncthreads();

        // ---- inner product: 64 FFMA per kk ----
#pragma unroll
        for (int kk = 0; kk < KC; kk++) {
            float a[8], w[8];
            float4 a0 = *(const float4*)&As_t[kk][ty * 8];
            float4 a1 = *(const float4*)&As_t[kk][ty * 8 + 4];
            a[0] = a0.x; a[1] = a0.y; a[2] = a0.z; a[3] = a0.w;
            a[4] = a1.x; a[5] = a1.y; a[6] = a1.z; a[7] = a1.w;
            float4 w0 = *(const float4*)&Wt[kk][tx * 8];
            float4 w1 = *(const float4*)&Wt[kk][tx * 8 + 4];
            w[0] = w0.x; w[1] = w0.y; w[2] = w0.z; w[3] = w0.w;
            w[4] = w1.x; w[5] = w1.y; w[6] = w1.z; w[7] = w1.w;
#pragma unroll
            for (int i = 0; i < 8; i++)
#pragma unroll
                for (int m = 0; m < 8; m++)
                    acc[i][m] += a[i] * w[m];
        }
    }

    // ---- epilogue: bias (+ relu), float4 stores ----
#pragma unroll
    for (int i = 0; i < 8; i++) {
        int r = rowbase + ty * 8 + i;
        if (r < nrows) {
            float o[8];
#pragma unroll
            for (int m = 0; m < 8; m++) {
                float v = acc[i][m] + bs[tx * 8 + m];
                o[m] = do_relu ? fmaxf(v, 0.f) : v;
            }
            float* op = out + (size_t)r * DIM + tx * 8;
            *(float4*)(op)     = make_float4(o[0], o[1], o[2], o[3]);
            *(float4*)(op + 4) = make_float4(o[4], o[5], o[6], o[7]);
        }
    }
}

// ---------------------------------------------------------------------------
extern "C" void kernel_launch(void* const* d_in, const int* in_sizes, int n_in,
                              void* d_out, int out_size)
{
    const float* x   = (const float*)d_in[0];
    const int*   src = (const int*)  d_in[1];
    const int*   dst = (const int*)  d_in[2];
    const float* wt  = (const float*)d_in[3];
    const float* Ws1 = (const float*)d_in[4];
    const float* Wn1 = (const float*)d_in[5];
    const float* b1  = (const float*)d_in[6];
    const float* Ws2 = (const float*)d_in[7];
    const float* Wn2 = (const float*)d_in[8];
    const float* b2  = (const float*)d_in[9];
    float* out = (float*)d_out;

    int E = in_sizes[1];

    int   *cnt, *row, *cur, *esrc;
    float *ew, *h1, *hn;
    cudaGetSymbolAddress((void**)&cnt,  g_cnt);
    cudaGetSymbolAddress((void**)&row,  g_row);
    cudaGetSymbolAddress((void**)&cur,  g_cur);
    cudaGetSymbolAddress((void**)&esrc, g_esrc);
    cudaGetSymbolAddress((void**)&ew,   g_ew);
    cudaGetSymbolAddress((void**)&h1,   g_h1);
    cudaGetSymbolAddress((void**)&hn,   g_hn);

    int eblocks = (E + 255) / 256;
    int gblocks = (N_NODES + TILE_ROWS - 1) / TILE_ROWS;      // 782
    int nwblocks = (N_NODES + 7) / 8;                          // 8 warps/block

    // ---- CSR build (by dst) ----
    zero_kernel<<<64, 256>>>((float4*)cnt, N_NODES / 4);
    hist_kernel<<<eblocks, 256>>>(dst, cnt, E);
    scan_kernel<<<1, SCAN_T>>>(cnt, row, cur);
    scatter_kernel<<<eblocks, 256>>>(src, dst, wt, cur, esrc, ew, E);

    // ---- layer 1 ----
    gather_kernel<<<nwblocks, 256>>>(x, row, esrc, ew, hn);
    sage_gemm<<<gblocks, 128>>>(x, hn, Ws1, Wn1, b1, h1, N_NODES, 1);

    // ---- layer 2 ----
    gather_kernel<<<nwblocks, 256>>>(h1, row, esrc, ew, hn);
    sage_gemm<<<gblocks, 128>>>(h1, hn, Ws2, Wn2, b2, out, N_NODES, 0);
}

// round 4
// speedup vs baseline: 1.1976x; 1.1268x over previous
#include <cuda_runtime.h>
#include <cstdint>

#define N_NODES 50000
#define E_MAX   625000
#define DIM     128

// ---------------------------------------------------------------------------
// Static device scratch (no runtime allocation)
// ---------------------------------------------------------------------------
__device__ int   g_cnt[N_NODES];                   // in-degree histogram
__device__ int   g_row[N_NODES + 1];               // CSR row offsets (by dst)
__device__ int   g_cur[N_NODES];                   // scatter cursors
__device__ int   g_bsum[256];                      // block partial sums (scan)
__device__ int   g_bofs[256];                      // block exclusive offsets
__device__ int   g_esrc[E_MAX];                    // CSR-reordered src ids
__device__ float g_ew[E_MAX];                      // CSR-reordered edge weights
__device__ float g_h1[(size_t)N_NODES * DIM];      // layer-1 activations
__device__ float g_hn[(size_t)N_NODES * DIM];      // neighbor means (h_neigh)

#define SCAN_BLK 256
#define SCAN_NB  ((N_NODES + SCAN_BLK - 1) / SCAN_BLK)   // 196

// ---------------------------------------------------------------------------
__global__ void zero_kernel(float4* __restrict__ p, int n4) {
    int i = blockIdx.x * blockDim.x + threadIdx.x;
    float4 z = make_float4(0.f, 0.f, 0.f, 0.f);
    for (; i < n4; i += gridDim.x * blockDim.x) p[i] = z;
}

// ---------------------------------------------------------------------------
// CSR build, step 1: histogram of dst
// ---------------------------------------------------------------------------
__global__ void hist_kernel(const int* __restrict__ dst, int* __restrict__ cnt, int E) {
    int i = blockIdx.x * blockDim.x + threadIdx.x;
    for (; i < E; i += gridDim.x * blockDim.x)
        atomicAdd(&cnt[dst[i]], 1);
}

// ---------------------------------------------------------------------------
// Scan pass A: per-block sums of cnt (coalesced)
// ---------------------------------------------------------------------------
__global__ void scan_bsum_kernel(const int* __restrict__ cnt, int* __restrict__ bsum) {
    __shared__ int sh[SCAN_BLK];
    int i = blockIdx.x * SCAN_BLK + threadIdx.x;
    int v = (i < N_NODES) ? cnt[i] : 0;
    sh[threadIdx.x] = v;
    __syncthreads();
    for (int off = SCAN_BLK / 2; off > 0; off >>= 1) {
        if (threadIdx.x < off) sh[threadIdx.x] += sh[threadIdx.x + off];
        __syncthreads();
    }
    if (threadIdx.x == 0) bsum[blockIdx.x] = sh[0];
}

// ---------------------------------------------------------------------------
// Scan pass B: exclusive scan over block sums (1 CTA); writes row[N]=total
// ---------------------------------------------------------------------------
__global__ void scan_bofs_kernel(const int* __restrict__ bsum,
                                 int* __restrict__ bofs,
                                 int* __restrict__ row) {
    __shared__ int sh[SCAN_BLK];
    int t = threadIdx.x;
    int v = (t < SCAN_NB) ? bsum[t] : 0;
    sh[t] = v;
    __syncthreads();
    for (int off = 1; off < SCAN_BLK; off <<= 1) {
        int u = 0;
        if (t >= off) u = sh[t - off];
        __syncthreads();
        if (t >= off) sh[t] += u;
        __syncthreads();
    }
    if (t < SCAN_NB) bofs[t] = sh[t] - v;           // exclusive
    if (t == SCAN_BLK - 1) row[N_NODES] = sh[t];    // total edges
}

// ---------------------------------------------------------------------------
// Scan pass C: per-block exclusive scan + offset; writes row and cur (coalesced)
// ---------------------------------------------------------------------------
__global__ void scan_write_kernel(const int* __restrict__ cnt,
                                  const int* __restrict__ bofs,
                                  int* __restrict__ row,
                                  int* __restrict__ cur) {
    __shared__ int sh[SCAN_BLK];
    int t = threadIdx.x;
    int i = blockIdx.x * SCAN_BLK + t;
    int v = (i < N_NODES) ? cnt[i] : 0;
    sh[t] = v;
    __syncthreads();
    for (int off = 1; off < SCAN_BLK; off <<= 1) {
        int u = 0;
        if (t >= off) u = sh[t - off];
        __syncthreads();
        if (t >= off) sh[t] += u;
        __syncthreads();
    }
    if (i < N_NODES) {
        int r = bofs[blockIdx.x] + sh[t] - v;       // exclusive prefix
        row[i] = r;
        cur[i] = r;
    }
}

// ---------------------------------------------------------------------------
// CSR build, step 3: scatter edges into CSR slots
// ---------------------------------------------------------------------------
__global__ void scatter_kernel(const int*   __restrict__ src,
                               const int*   __restrict__ dst,
                               const float* __restrict__ wt,
                               int*   __restrict__ cur,
                               int*   __restrict__ esrc,
                               float* __restrict__ ew,
                               int E)
{
    int i = blockIdx.x * blockDim.x + threadIdx.x;
    for (; i < E; i += gridDim.x * blockDim.x) {
        int p = atomicAdd(&cur[dst[i]], 1);
        esrc[p] = src[i];
        ew[p]   = wt[i];
    }
}

// ---------------------------------------------------------------------------
// Gather v2: one warp per destination node.
//   hn[n] = (1/max(deg,1)) * sum_e w_e * h[src_e]
// Edge ids/weights are batch-loaded into lanes (up to 32 at a time) and
// broadcast via shfl -> no per-iteration index-load chain. Row loads issued
// 4 deep (MLP=4). lane l owns dims [4l, 4l+4).
// ---------------------------------------------------------------------------
__global__ void gather_kernel(const float* __restrict__ h,
                              const int*   __restrict__ row,
                              const int*   __restrict__ esrc,
                              const float* __restrict__ ew,
                              float*       __restrict__ hn)
{
    int warp = (blockIdx.x * blockDim.x + threadIdx.x) >> 5;
    int lane = threadIdx.x & 31;
    if (warp >= N_NODES) return;

    int rs = row[warp];
    int re = row[warp + 1];

    float4 acc = make_float4(0.f, 0.f, 0.f, 0.f);

    for (int base = rs; base < re; base += 32) {
        int cnt = re - base; if (cnt > 32) cnt = 32;
        int   s_l = 0; float w_l = 0.f;
        if (lane < cnt) { s_l = esrc[base + lane]; w_l = ew[base + lane]; }

        for (int j = 0; j < cnt; j += 4) {
            int valid = cnt - j; if (valid > 4) valid = 4;
            float4 v[4]; float wj[4];
#pragma unroll
            for (int u = 0; u < 4; u++) {
                int   s = __shfl_sync(0xffffffffu, s_l, j + u);
                float w = __shfl_sync(0xffffffffu, w_l, j + u);
                if (u < valid) {
                    v[u]  = *(const float4*)(h + (size_t)s * DIM + lane * 4);
                    wj[u] = w;
                }
            }
#pragma unroll
            for (int u = 0; u < 4; u++) {
                if (u < valid) {
                    acc.x += wj[u] * v[u].x;
                    acc.y += wj[u] * v[u].y;
                    acc.z += wj[u] * v[u].z;
                    acc.w += wj[u] * v[u].w;
                }
            }
        }
    }

    float inv = 1.0f / fmaxf((float)(re - rs), 1.0f);
    acc.x *= inv; acc.y *= inv; acc.z *= inv; acc.w *= inv;
    *(float4*)(hn + (size_t)warp * DIM + lane * 4) = acc;
}

// ---------------------------------------------------------------------------
// Fused SAGE GEMM v3: 64x128 CTA tile, 128 threads, 8x8 thread tile.
//   out[r, j] = sum_k h[r,k]*Ws[j,k] + hn[r,k]*Wn[j,k] + b[j]
// K = 256 (self half then neighbor half), KC = 32.
// A tile stored TRANSPOSED: As_t[kk][row] -> a-fragment = 2 broadcast LDS.128.
// ---------------------------------------------------------------------------
#define TILE_ROWS 64
#define KC 32
#define AST_STRIDE 68   // float4-aligned, bank shift 4 per kk

__global__ __launch_bounds__(128, 3)
void sage_gemm(const float* __restrict__ Aself,
               const float* __restrict__ Aneigh,   // already deg-scaled
               const float* __restrict__ Ws,
               const float* __restrict__ Wn,
               const float* __restrict__ bias,
               float*       __restrict__ out,
               int nrows, int do_relu)
{
    __shared__ float As_t[KC][AST_STRIDE];    // [kk][row]
    __shared__ float Wt[KC][DIM + 4];         // [kk][j]
    __shared__ float bs[DIM];

    int tid = threadIdx.x;
    int tx = tid & 15;        // column group: cols [8*tx, 8*tx+8)
    int ty = tid >> 4;        // row group:    rows [8*ty, 8*ty+8)
    int rowbase = blockIdx.x * TILE_ROWS;

    if (tid < DIM) bs[tid] = bias[tid];

    float acc[8][8];
#pragma unroll
    for (int i = 0; i < 8; i++)
#pragma unroll
        for (int m = 0; m < 8; m++) acc[i][m] = 0.f;

    for (int kc = 0; kc < 2 * DIM; kc += KC) {
        __syncthreads();

        // ---- W chunk (transposed): Wt[kk][j] = W[j][kb+kk] ----
        {
            const float* W = (kc < DIM) ? Ws : Wn;
            int kb = kc & (DIM - 1);
#pragma unroll
            for (int it = 0; it < (KC * DIM) / 128; it++) {
                int idx = tid + it * 128;       // 0..4095
                int kk = idx & (KC - 1);
                int j  = idx >> 5;
                Wt[kk][j] = W[j * DIM + kb + kk];
            }
        }

        // ---- A chunk, transposed into As_t[kk][row] ----
        {
            const float* A = (kc < DIM) ? Aself : Aneigh;
            int kb = kc & (DIM - 1);
#pragma unroll
            for (int it = 0; it < 4; it++) {
                int q = tid + it * 128;         // 0..511
                int lrow = q >> 3;              // 0..63
                int lk   = (q & 7) * 4;         // 0,4,...,28
                int grow = rowbase + lrow;
                if (grow > nrows - 1) grow = nrows - 1;
                float4 v = *(const float4*)(A + (size_t)grow * DIM + kb + lk);
                As_t[lk + 0][lrow] = v.x;
                As_t[lk + 1][lrow] = v.y;
                As_t[lk + 2][lrow] = v.z;
                As_t[lk + 3][lrow] = v.w;
            }
        }
        __syncthreads();

        // ---- inner product: 64 FFMA per kk ----
#pragma unroll
        for (int kk = 0; kk < KC; kk++) {
            float a[8], w[8];
            float4 a0 = *(const float4*)&As_t[kk][ty * 8];
            float4 a1 = *(const float4*)&As_t[kk][ty * 8 + 4];
            a[0] = a0.x; a[1] = a0.y; a[2] = a0.z; a[3] = a0.w;
            a[4] = a1.x; a[5] = a1.y; a[6] = a1.z; a[7] = a1.w;
            float4 w0 = *(const float4*)&Wt[kk][tx * 8];
            float4 w1 = *(const float4*)&Wt[kk][tx * 8 + 4];
            w[0] = w0.x; w[1] = w0.y; w[2] = w0.z; w[3] = w0.w;
            w[4] = w1.x; w[5] = w1.y; w[6] = w1.z; w[7] = w1.w;
#pragma unroll
            for (int i = 0; i < 8; i++)
#pragma unroll
                for (int m = 0; m < 8; m++)
                    acc[i][m] += a[i] * w[m];
        }
    }

    // ---- epilogue ----
#pragma unroll
    for (int i = 0; i < 8; i++) {
        int r = rowbase + ty * 8 + i;
        if (r < nrows) {
            float o[8];
#pragma unroll
            for (int m = 0; m < 8; m++) {
                float v = acc[i][m] + bs[tx * 8 + m];
                o[m] = do_relu ? fmaxf(v, 0.f) : v;
            }
            float* op = out + (size_t)r * DIM + tx * 8;
            *(float4*)(op)     = make_float4(o[0], o[1], o[2], o[3]);
            *(float4*)(op + 4) = make_float4(o[4], o[5], o[6], o[7]);
        }
    }
}

// ---------------------------------------------------------------------------
extern "C" void kernel_launch(void* const* d_in, const int* in_sizes, int n_in,
                              void* d_out, int out_size)
{
    const float* x   = (const float*)d_in[0];
    const int*   src = (const int*)  d_in[1];
    const int*   dst = (const int*)  d_in[2];
    const float* wt  = (const float*)d_in[3];
    const float* Ws1 = (const float*)d_in[4];
    const float* Wn1 = (const float*)d_in[5];
    const float* b1  = (const float*)d_in[6];
    const float* Ws2 = (const float*)d_in[7];
    const float* Wn2 = (const float*)d_in[8];
    const float* b2  = (const float*)d_in[9];
    float* out = (float*)d_out;

    int E = in_sizes[1];

    int   *cnt, *row, *cur, *bsum, *bofs, *esrc;
    float *ew, *h1, *hn;
    cudaGetSymbolAddress((void**)&cnt,  g_cnt);
    cudaGetSymbolAddress((void**)&row,  g_row);
    cudaGetSymbolAddress((void**)&cur,  g_cur);
    cudaGetSymbolAddress((void**)&bsum, g_bsum);
    cudaGetSymbolAddress((void**)&bofs, g_bofs);
    cudaGetSymbolAddress((void**)&esrc, g_esrc);
    cudaGetSymbolAddress((void**)&ew,   g_ew);
    cudaGetSymbolAddress((void**)&h1,   g_h1);
    cudaGetSymbolAddress((void**)&hn,   g_hn);

    int eblocks = (E + 255) / 256;
    int gblocks = (N_NODES + TILE_ROWS - 1) / TILE_ROWS;
    int nwblocks = (N_NODES + 7) / 8;          // 8 warps/block for gather

    // ---- CSR build (by dst) ----
    zero_kernel<<<64, 256>>>((float4*)cnt, N_NODES / 4);
    hist_kernel<<<eblocks, 256>>>(dst, cnt, E);
    scan_bsum_kernel<<<SCAN_NB, SCAN_BLK>>>(cnt, bsum);
    scan_bofs_kernel<<<1, SCAN_BLK>>>(bsum, bofs, row);
    scan_write_kernel<<<SCAN_NB, SCAN_BLK>>>(cnt, bofs, row, cur);
    scatter_kernel<<<eblocks, 256>>>(src, dst, wt, cur, esrc, ew, E);

    // ---- layer 1 ----
    gather_kernel<<<nwblocks, 256>>>(x, row, esrc, ew, hn);
    sage_gemm<<<gblocks, 128>>>(x, hn, Ws1, Wn1, b1, h1, N_NODES, 1);

    // ---- layer 2 ----
    gather_kernel<<<nwblocks, 256>>>(h1, row, esrc, ew, hn);
    sage_gemm<<<gblocks, 128>>>(h1, hn, Ws2, Wn2, b2, out, N_NODES, 0);
}

// round 5
// speedup vs baseline: 1.2317x; 1.0285x over previous
#include <cuda_runtime.h>
#include <cstdint>

#define N_NODES 50000
#define E_MAX   625000
#define DIM     128

// ---------------------------------------------------------------------------
// Static device scratch (no runtime allocation)
// ---------------------------------------------------------------------------
__device__ int   g_cnt[N_NODES];                   // in-degree histogram
__device__ int   g_row[N_NODES + 1];               // CSR row offsets (by dst)
__device__ int   g_cur[N_NODES];                   // scatter cursors
__device__ int   g_bsum[256];                      // block partial sums (scan)
__device__ int   g_bofs[256];                      // block exclusive offsets
__device__ int   g_esrc[E_MAX];                    // CSR-reordered src ids
__device__ float g_ew[E_MAX];                      // CSR-reordered edge weights
__device__ float g_h1[(size_t)N_NODES * DIM];      // layer-1 activations
__device__ float g_hn[(size_t)N_NODES * DIM];      // neighbor means (h_neigh)

#define SCAN_BLK 256
#define SCAN_NB  ((N_NODES + SCAN_BLK - 1) / SCAN_BLK)   // 196

// ---------------------------------------------------------------------------
__global__ void zero_kernel(float4* __restrict__ p, int n4) {
    int i = blockIdx.x * blockDim.x + threadIdx.x;
    float4 z = make_float4(0.f, 0.f, 0.f, 0.f);
    for (; i < n4; i += gridDim.x * blockDim.x) p[i] = z;
}

// ---------------------------------------------------------------------------
// CSR build, step 1: histogram of dst
// ---------------------------------------------------------------------------
__global__ void hist_kernel(const int* __restrict__ dst, int* __restrict__ cnt, int E) {
    int i = blockIdx.x * blockDim.x + threadIdx.x;
    for (; i < E; i += gridDim.x * blockDim.x)
        atomicAdd(&cnt[dst[i]], 1);
}

// ---------------------------------------------------------------------------
// Scan pass A: per-block sums of cnt (coalesced)
// ---------------------------------------------------------------------------
__global__ void scan_bsum_kernel(const int* __restrict__ cnt, int* __restrict__ bsum) {
    __shared__ int sh[SCAN_BLK];
    int i = blockIdx.x * SCAN_BLK + threadIdx.x;
    int v = (i < N_NODES) ? cnt[i] : 0;
    sh[threadIdx.x] = v;
    __syncthreads();
    for (int off = SCAN_BLK / 2; off > 0; off >>= 1) {
        if (threadIdx.x < off) sh[threadIdx.x] += sh[threadIdx.x + off];
        __syncthreads();
    }
    if (threadIdx.x == 0) bsum[blockIdx.x] = sh[0];
}

// ---------------------------------------------------------------------------
// Scan pass B: exclusive scan over block sums (1 CTA); writes row[N]=total
// ---------------------------------------------------------------------------
__global__ void scan_bofs_kernel(const int* __restrict__ bsum,
                                 int* __restrict__ bofs,
                                 int* __restrict__ row) {
    __shared__ int sh[SCAN_BLK];
    int t = threadIdx.x;
    int v = (t < SCAN_NB) ? bsum[t] : 0;
    sh[t] = v;
    __syncthreads();
    for (int off = 1; off < SCAN_BLK; off <<= 1) {
        int u = 0;
        if (t >= off) u = sh[t - off];
        __syncthreads();
        if (t >= off) sh[t] += u;
        __syncthreads();
    }
    if (t < SCAN_NB) bofs[t] = sh[t] - v;           // exclusive
    if (t == SCAN_BLK - 1) row[N_NODES] = sh[t];    // total edges
}

// ---------------------------------------------------------------------------
// Scan pass C: per-block exclusive scan + offset; writes row and cur
// ---------------------------------------------------------------------------
__global__ void scan_write_kernel(const int* __restrict__ cnt,
                                  const int* __restrict__ bofs,
                                  int* __restrict__ row,
                                  int* __restrict__ cur) {
    __shared__ int sh[SCAN_BLK];
    int t = threadIdx.x;
    int i = blockIdx.x * SCAN_BLK + t;
    int v = (i < N_NODES) ? cnt[i] : 0;
    sh[t] = v;
    __syncthreads();
    for (int off = 1; off < SCAN_BLK; off <<= 1) {
        int u = 0;
        if (t >= off) u = sh[t - off];
        __syncthreads();
        if (t >= off) sh[t] += u;
        __syncthreads();
    }
    if (i < N_NODES) {
        int r = bofs[blockIdx.x] + sh[t] - v;       // exclusive prefix
        row[i] = r;
        cur[i] = r;
    }
}

// ---------------------------------------------------------------------------
// CSR build, step 3: scatter edges into CSR slots
// ---------------------------------------------------------------------------
__global__ void scatter_kernel(const int*   __restrict__ src,
                               const int*   __restrict__ dst,
                               const float* __restrict__ wt,
                               int*   __restrict__ cur,
                               int*   __restrict__ esrc,
                               float* __restrict__ ew,
                               int E)
{
    int i = blockIdx.x * blockDim.x + threadIdx.x;
    for (; i < E; i += gridDim.x * blockDim.x) {
        int p = atomicAdd(&cur[dst[i]], 1);
        esrc[p] = src[i];
        ew[p]   = wt[i];
    }
}

// ---------------------------------------------------------------------------
// Gather v2: one warp per destination node; shfl-broadcast edge batch, MLP=4.
// ---------------------------------------------------------------------------
__global__ void gather_kernel(const float* __restrict__ h,
                              const int*   __restrict__ row,
                              const int*   __restrict__ esrc,
                              const float* __restrict__ ew,
                              float*       __restrict__ hn)
{
    int warp = (blockIdx.x * blockDim.x + threadIdx.x) >> 5;
    int lane = threadIdx.x & 31;
    if (warp >= N_NODES) return;

    int rs = row[warp];
    int re = row[warp + 1];

    float4 acc = make_float4(0.f, 0.f, 0.f, 0.f);

    for (int base = rs; base < re; base += 32) {
        int cnt = re - base; if (cnt > 32) cnt = 32;
        int   s_l = 0; float w_l = 0.f;
        if (lane < cnt) { s_l = esrc[base + lane]; w_l = ew[base + lane]; }

        for (int j = 0; j < cnt; j += 4) {
            int valid = cnt - j; if (valid > 4) valid = 4;
            float4 v[4]; float wj[4];
#pragma unroll
            for (int u = 0; u < 4; u++) {
                int   s = __shfl_sync(0xffffffffu, s_l, j + u);
                float w = __shfl_sync(0xffffffffu, w_l, j + u);
                if (u < valid) {
                    v[u]  = *(const float4*)(h + (size_t)s * DIM + lane * 4);
                    wj[u] = w;
                }
            }
#pragma unroll
            for (int u = 0; u < 4; u++) {
                if (u < valid) {
                    acc.x += wj[u] * v[u].x;
                    acc.y += wj[u] * v[u].y;
                    acc.z += wj[u] * v[u].z;
                    acc.w += wj[u] * v[u].w;
                }
            }
        }
    }

    float inv = 1.0f / fmaxf((float)(re - rs), 1.0f);
    acc.x *= inv; acc.y *= inv; acc.z *= inv; acc.w *= inv;
    *(float4*)(hn + (size_t)warp * DIM + lane * 4) = acc;
}

// ---------------------------------------------------------------------------
// Fused SAGE GEMM v4: 64x128 CTA tile, 128 threads, 8x8 thread tile,
// inner loop on packed fma.rn.f32x2 (FFMA2, 2x fp32 rate on Blackwell —
// ptxas never emits it from C++, PTX only).
//   out[r, j] = sum_k h[r,k]*Ws[j,k] + hn[r,k]*Wn[j,k] + b[j]
// Accumulators: 32 packed f32x2 pairs (pairing along output columns).
// ---------------------------------------------------------------------------
#define TILE_ROWS 64
#define KC 32
#define AST_STRIDE 68   // float4-aligned, bank shift 4 per kk

__global__ __launch_bounds__(128, 3)
void sage_gemm(const float* __restrict__ Aself,
               const float* __restrict__ Aneigh,   // already deg-scaled
               const float* __restrict__ Ws,
               const float* __restrict__ Wn,
               const float* __restrict__ bias,
               float*       __restrict__ out,
               int nrows, int do_relu)
{
    __shared__ float As_t[KC][AST_STRIDE];    // [kk][row]
    __shared__ float Wt[KC][DIM + 4];         // [kk][j]
    __shared__ float bs[DIM];

    int tid = threadIdx.x;
    int tx = tid & 15;        // column group: cols [8*tx, 8*tx+8)
    int ty = tid >> 4;        // row group:    rows [8*ty, 8*ty+8)
    int rowbase = blockIdx.x * TILE_ROWS;

    if (tid < DIM) bs[tid] = bias[tid];

    // 8 rows x 4 column-pairs of packed f32x2 accumulators
    unsigned long long accp[8][4];
#pragma unroll
    for (int i = 0; i < 8; i++)
#pragma unroll
        for (int m = 0; m < 4; m++) accp[i][m] = 0ull;

    for (int kc = 0; kc < 2 * DIM; kc += KC) {
        __syncthreads();

        // ---- W chunk (transposed): Wt[kk][j] = W[j][kb+kk] ----
        {
            const float* W = (kc < DIM) ? Ws : Wn;
            int kb = kc & (DIM - 1);
#pragma unroll
            for (int it = 0; it < (KC * DIM) / 128; it++) {
                int idx = tid + it * 128;       // 0..4095
                int kk = idx & (KC - 1);
                int j  = idx >> 5;
                Wt[kk][j] = W[j * DIM + kb + kk];
            }
        }

        // ---- A chunk, transposed into As_t[kk][row] ----
        {
            const float* A = (kc < DIM) ? Aself : Aneigh;
            int kb = kc & (DIM - 1);
#pragma unroll
            for (int it = 0; it < 4; it++) {
                int q = tid + it * 128;         // 0..511
                int lrow = q >> 3;              // 0..63
                int lk   = (q & 7) * 4;         // 0,4,...,28
                int grow = rowbase + lrow;
                if (grow > nrows - 1) grow = nrows - 1;
                float4 v = *(const float4*)(A + (size_t)grow * DIM + kb + lk);
                As_t[lk + 0][lrow] = v.x;
                As_t[lk + 1][lrow] = v.y;
                As_t[lk + 2][lrow] = v.z;
                As_t[lk + 3][lrow] = v.w;
            }
        }
        __syncthreads();

        // ---- inner product: 32 FFMA2 per kk per thread ----
#pragma unroll
        for (int kk = 0; kk < KC; kk++) {
            float4 a0 = *(const float4*)&As_t[kk][ty * 8];
            float4 a1 = *(const float4*)&As_t[kk][ty * 8 + 4];
            float4 w0 = *(const float4*)&Wt[kk][tx * 8];
            float4 w1 = *(const float4*)&Wt[kk][tx * 8 + 4];

            unsigned long long wp[4];
            asm("mov.b64 %0, {%1, %2};" : "=l"(wp[0]) : "f"(w0.x), "f"(w0.y));
            asm("mov.b64 %0, {%1, %2};" : "=l"(wp[1]) : "f"(w0.z), "f"(w0.w));
            asm("mov.b64 %0, {%1, %2};" : "=l"(wp[2]) : "f"(w1.x), "f"(w1.y));
            asm("mov.b64 %0, {%1, %2};" : "=l"(wp[3]) : "f"(w1.z), "f"(w1.w));

            float av[8];
            av[0] = a0.x; av[1] = a0.y; av[2] = a0.z; av[3] = a0.w;
            av[4] = a1.x; av[5] = a1.y; av[6] = a1.z; av[7] = a1.w;

#pragma unroll
            for (int i = 0; i < 8; i++) {
                unsigned long long ap;
                asm("mov.b64 %0, {%1, %1};" : "=l"(ap) : "f"(av[i]));
#pragma unroll
                for (int m = 0; m < 4; m++) {
                    asm("fma.rn.f32x2 %0, %1, %2, %0;"
                        : "+l"(accp[i][m]) : "l"(ap), "l"(wp[m]));
                }
            }
        }
    }

    // ---- epilogue: unpack pairs, bias (+ relu), float4 stores ----
#pragma unroll
    for (int i = 0; i < 8; i++) {
        int r = rowbase + ty * 8 + i;
        if (r < nrows) {
            float o[8];
#pragma unroll
            for (int m = 0; m < 4; m++) {
                float lo, hi;
                asm("mov.b64 {%0, %1}, %2;" : "=f"(lo), "=f"(hi) : "l"(accp[i][m]));
                float v0 = lo + bs[tx * 8 + 2 * m];
                float v1 = hi + bs[tx * 8 + 2 * m + 1];
                o[2 * m]     = do_relu ? fmaxf(v0, 0.f) : v0;
                o[2 * m + 1] = do_relu ? fmaxf(v1, 0.f) : v1;
            }
            float* op = out + (size_t)r * DIM + tx * 8;
            *(float4*)(op)     = make_float4(o[0], o[1], o[2], o[3]);
            *(float4*)(op + 4) = make_float4(o[4], o[5], o[6], o[7]);
        }
    }
}

// ---------------------------------------------------------------------------
extern "C" void kernel_launch(void* const* d_in, const int* in_sizes, int n_in,
                              void* d_out, int out_size)
{
    const float* x   = (const float*)d_in[0];
    const int*   src = (const int*)  d_in[1];
    const int*   dst = (const int*)  d_in[2];
    const float* wt  = (const float*)d_in[3];
    const float* Ws1 = (const float*)d_in[4];
    const float* Wn1 = (const float*)d_in[5];
    const float* b1  = (const float*)d_in[6];
    const float* Ws2 = (const float*)d_in[7];
    const float* Wn2 = (const float*)d_in[8];
    const float* b2  = (const float*)d_in[9];
    float* out = (float*)d_out;

    int E = in_sizes[1];

    int   *cnt, *row, *cur, *bsum, *bofs, *esrc;
    float *ew, *h1, *hn;
    cudaGetSymbolAddress((void**)&cnt,  g_cnt);
    cudaGetSymbolAddress((void**)&row,  g_row);
    cudaGetSymbolAddress((void**)&cur,  g_cur);
    cudaGetSymbolAddress((void**)&bsum, g_bsum);
    cudaGetSymbolAddress((void**)&bofs, g_bofs);
    cudaGetSymbolAddress((void**)&esrc, g_esrc);
    cudaGetSymbolAddress((void**)&ew,   g_ew);
    cudaGetSymbolAddress((void**)&h1,   g_h1);
    cudaGetSymbolAddress((void**)&hn,   g_hn);

    int eblocks = (E + 255) / 256;
    int gblocks = (N_NODES + TILE_ROWS - 1) / TILE_ROWS;
    int nwblocks = (N_NODES + 7) / 8;          // 8 warps/block for gather

    // ---- CSR build (by dst) ----
    zero_kernel<<<64, 256>>>((float4*)cnt, N_NODES / 4);
    hist_kernel<<<eblocks, 256>>>(dst, cnt, E);
    scan_bsum_kernel<<<SCAN_NB, SCAN_BLK>>>(cnt, bsum);
    scan_bofs_kernel<<<1, SCAN_BLK>>>(bsum, bofs, row);
    scan_write_kernel<<<SCAN_NB, SCAN_BLK>>>(cnt, bofs, row, cur);
    scatter_kernel<<<eblocks, 256>>>(src, dst, wt, cur, esrc, ew, E);

    // ---- layer 1 ----
    gather_kernel<<<nwblocks, 256>>>(x, row, esrc, ew, hn);
    sage_gemm<<<gblocks, 128>>>(x, hn, Ws1, Wn1, b1, h1, N_NODES, 1);

    // ---- layer 2 ----
    gather_kernel<<<nwblocks, 256>>>(h1, row, esrc, ew, hn);
    sage_gemm<<<gblocks, 128>>>(h1, hn, Ws2, Wn2, b2, out, N_NODES, 0);
}

// round 7
// speedup vs baseline: 1.8230x; 1.4801x over previous
#include <cuda_runtime.h>
#include <cuda_bf16.h>
#include <cstdint>

#define N_NODES 50000
#define E_MAX   625000
#define DIM     128

// ---------------------------------------------------------------------------
// Static device scratch (no runtime allocation)
// ---------------------------------------------------------------------------
__device__ int   g_cnt[N_NODES];
__device__ int   g_row[N_NODES + 1];
__device__ int   g_cur[N_NODES];
__device__ int   g_bsum[256];
__device__ int   g_bofs[256];
__device__ int   g_esrc[E_MAX];
__device__ float g_ew[E_MAX];
__device__ float g_h1[(size_t)N_NODES * DIM];
__device__ float g_hn[(size_t)N_NODES * DIM];

#define SCAN_BLK 256
#define SCAN_NB  ((N_NODES + SCAN_BLK - 1) / SCAN_BLK)   // 196

// ---------------------------------------------------------------------------
__global__ void zero_kernel(float4* __restrict__ p, int n4) {
    int i = blockIdx.x * blockDim.x + threadIdx.x;
    float4 z = make_float4(0.f, 0.f, 0.f, 0.f);
    for (; i < n4; i += gridDim.x * blockDim.x) p[i] = z;
}

__global__ void hist_kernel(const int* __restrict__ dst, int* __restrict__ cnt, int E) {
    int i = blockIdx.x * blockDim.x + threadIdx.x;
    for (; i < E; i += gridDim.x * blockDim.x)
        atomicAdd(&cnt[dst[i]], 1);
}

__global__ void scan_bsum_kernel(const int* __restrict__ cnt, int* __restrict__ bsum) {
    __shared__ int sh[SCAN_BLK];
    int i = blockIdx.x * SCAN_BLK + threadIdx.x;
    int v = (i < N_NODES) ? cnt[i] : 0;
    sh[threadIdx.x] = v;
    __syncthreads();
    for (int off = SCAN_BLK / 2; off > 0; off >>= 1) {
        if (threadIdx.x < off) sh[threadIdx.x] += sh[threadIdx.x + off];
        __syncthreads();
    }
    if (threadIdx.x == 0) bsum[blockIdx.x] = sh[0];
}

__global__ void scan_bofs_kernel(const int* __restrict__ bsum,
                                 int* __restrict__ bofs,
                                 int* __restrict__ row) {
    __shared__ int sh[SCAN_BLK];
    int t = threadIdx.x;
    int v = (t < SCAN_NB) ? bsum[t] : 0;
    sh[t] = v;
    __syncthreads();
    for (int off = 1; off < SCAN_BLK; off <<= 1) {
        int u = 0;
        if (t >= off) u = sh[t - off];
        __syncthreads();
        if (t >= off) sh[t] += u;
        __syncthreads();
    }
    if (t < SCAN_NB) bofs[t] = sh[t] - v;
    if (t == SCAN_BLK - 1) row[N_NODES] = sh[t];
}

__global__ void scan_write_kernel(const int* __restrict__ cnt,
                                  const int* __restrict__ bofs,
                                  int* __restrict__ row,
                                  int* __restrict__ cur) {
    __shared__ int sh[SCAN_BLK];
    int t = threadIdx.x;
    int i = blockIdx.x * SCAN_BLK + t;
    int v = (i < N_NODES) ? cnt[i] : 0;
    sh[t] = v;
    __syncthreads();
    for (int off = 1; off < SCAN_BLK; off <<= 1) {
        int u = 0;
        if (t >= off) u = sh[t - off];
        __syncthreads();
        if (t >= off) sh[t] += u;
        __syncthreads();
    }
    if (i < N_NODES) {
        int r = bofs[blockIdx.x] + sh[t] - v;
        row[i] = r;
        cur[i] = r;
    }
}

__global__ void scatter_kernel(const int*   __restrict__ src,
                               const int*   __restrict__ dst,
                               const float* __restrict__ wt,
                               int*   __restrict__ cur,
                               int*   __restrict__ esrc,
                               float* __restrict__ ew,
                               int E)
{
    int i = blockIdx.x * blockDim.x + threadIdx.x;
    for (; i < E; i += gridDim.x * blockDim.x) {
        int p = atomicAdd(&cur[dst[i]], 1);
        esrc[p] = src[i];
        ew[p]   = wt[i];
    }
}

// ---------------------------------------------------------------------------
// Gather v2: one warp per destination node; shfl-broadcast edge batch, MLP=4.
// ---------------------------------------------------------------------------
__global__ void gather_kernel(const float* __restrict__ h,
                              const int*   __restrict__ row,
                              const int*   __restrict__ esrc,
                              const float* __restrict__ ew,
                              float*       __restrict__ hn)
{
    int warp = (blockIdx.x * blockDim.x + threadIdx.x) >> 5;
    int lane = threadIdx.x & 31;
    if (warp >= N_NODES) return;

    int rs = row[warp];
    int re = row[warp + 1];

    float4 acc = make_float4(0.f, 0.f, 0.f, 0.f);

    for (int base = rs; base < re; base += 32) {
        int cnt = re - base; if (cnt > 32) cnt = 32;
        int   s_l = 0; float w_l = 0.f;
        if (lane < cnt) { s_l = esrc[base + lane]; w_l = ew[base + lane]; }

        for (int j = 0; j < cnt; j += 4) {
            int valid = cnt - j; if (valid > 4) valid = 4;
            float4 v[4]; float wj[4];
#pragma unroll
            for (int u = 0; u < 4; u++) {
                int   s = __shfl_sync(0xffffffffu, s_l, j + u);
                float w = __shfl_sync(0xffffffffu, w_l, j + u);
                if (u < valid) {
                    v[u]  = *(const float4*)(h + (size_t)s * DIM + lane * 4);
                    wj[u] = w;
                }
            }
#pragma unroll
            for (int u = 0; u < 4; u++) {
                if (u < valid) {
                    acc.x += wj[u] * v[u].x;
                    acc.y += wj[u] * v[u].y;
                    acc.z += wj[u] * v[u].z;
                    acc.w += wj[u] * v[u].w;
                }
            }
        }
    }

    float inv = 1.0f / fmaxf((float)(re - rs), 1.0f);
    acc.x *= inv; acc.y *= inv; acc.z *= inv; acc.w *= inv;
    *(float4*)(hn + (size_t)warp * DIM + lane * 4) = acc;
}

// ---------------------------------------------------------------------------
// SAGE GEMM v6: warp-level mma.sync bf16 split-precision (hi+lo; drop lo*lo).
// Works on generic sm_100 target (no tcgen05).
//   out[r, j] = sum_k h[r,k]*Ws[j,k] + hn[r,k]*Wn[j,k] + b[j]
// CTA: 128x128 tile, 256 threads = 8 warps as 4(m) x 2(n).
// Warp tile 32x64: 2 m-tiles (16) x 8 n-tiles (8).
// K = 256 in 8 chunks of 32; per chunk convert fp32 -> bf16 hi/lo in smem,
// then mma.m16n8k16 for 3 terms (hi*hi, hi*lo, lo*hi), fp32 accumulation.
// ---------------------------------------------------------------------------
#define MM_TILE 128
#define STR 40   // smem row stride in bf16 elems (80B: 16B-aligned, conflict-free ldmatrix)

__device__ __forceinline__ void ldm4(uint32_t (&r)[4], uint32_t addr) {
    asm volatile("ldmatrix.sync.aligned.m8n8.x4.shared.b16 {%0,%1,%2,%3}, [%4];"
                 : "=r"(r[0]), "=r"(r[1]), "=r"(r[2]), "=r"(r[3]) : "r"(addr));
}
__device__ __forceinline__ void mma_bf16(float (&c)[4], const uint32_t (&a)[4],
                                         uint32_t b0, uint32_t b1) {
    asm volatile("mma.sync.aligned.m16n8k16.row.col.f32.bf16.bf16.f32 "
                 "{%0,%1,%2,%3}, {%4,%5,%6,%7}, {%8,%9}, {%0,%1,%2,%3};"
                 : "+f"(c[0]), "+f"(c[1]), "+f"(c[2]), "+f"(c[3])
                 : "r"(a[0]), "r"(a[1]), "r"(a[2]), "r"(a[3]), "r"(b0), "r"(b1));
}
__device__ __forceinline__ uint32_t smem_u32(const void* p) {
    uint32_t a;
    asm("{ .reg .u64 t; cvta.to.shared.u64 t, %1; cvt.u32.u64 %0, t; }" : "=r"(a) : "l"(p));
    return a;
}
__device__ __forceinline__ uint32_t packbf(float a, float b) {
    __nv_bfloat162 t = __floats2bfloat162_rn(a, b);
    return *(uint32_t*)&t;
}
// fp32 pair -> (hi pair, lo pair) packed bf16x2
__device__ __forceinline__ void split2(float x, float y, uint32_t& hi, uint32_t& lo) {
    float hx = __bfloat162float(__float2bfloat16_rn(x));
    float hy = __bfloat162float(__float2bfloat16_rn(y));
    hi = packbf(hx, hy);
    lo = packbf(x - hx, y - hy);
}

__global__ void sage_gemm_mma(const float* __restrict__ Aself,
                              const float* __restrict__ Aneigh,  // already deg-scaled
                              const float* __restrict__ Ws,
                              const float* __restrict__ Wn,
                              const float* __restrict__ bias,
                              float*       __restrict__ out,
                              int nrows, int do_relu)
{
    __shared__ __align__(16) unsigned short Ah[MM_TILE * STR];
    __shared__ __align__(16) unsigned short Al[MM_TILE * STR];
    __shared__ __align__(16) unsigned short Bh[MM_TILE * STR];
    __shared__ __align__(16) unsigned short Bl[MM_TILE * STR];
    __shared__ float bs[DIM];

    int tid  = threadIdx.x;
    int wid  = tid >> 5;
    int lane = tid & 31;
    int warp_m = (wid & 3) * 32;   // rows owned by warp: [warp_m, warp_m+32)
    int warp_n = (wid >> 2) * 64;  // cols owned by warp: [warp_n, warp_n+64)
    int rowbase = blockIdx.x * MM_TILE;

    if (tid < DIM) bs[tid] = bias[tid];

    float acc[2][8][4];
#pragma unroll
    for (int mt = 0; mt < 2; mt++)
#pragma unroll
        for (int nt = 0; nt < 8; nt++)
#pragma unroll
            for (int e = 0; e < 4; e++) acc[mt][nt][e] = 0.f;

    uint32_t ah_base = smem_u32(Ah), al_base = smem_u32(Al);
    uint32_t bh_base = smem_u32(Bh), bl_base = smem_u32(Bl);

    // ldmatrix lane address components (in elements)
    int a_r = lane & 15;                 // row within m-tile
    int a_c = (lane >> 4) << 3;          // 0 or 8 (k offset)
    int b_g = lane >> 3;                 // group 0..3
    int b_r = lane & 7;
    int b_nofs = ((b_g >> 1) << 3) + b_r;   // n offset within 16-wide pair
    int b_kofs = (b_g & 1) << 3;            // 0 or 8

    for (int chunk = 0; chunk < 8; chunk++) {
        const float* As; const float* W; int kb = (chunk & 3) * 32;
        if (chunk < 4) { As = Aself;  W = Ws; }
        else           { As = Aneigh; W = Wn; }

        __syncthreads();   // protect previous chunk's reads

        // ---- convert A chunk: 128 rows x 32 cols -> hi/lo ----
#pragma unroll
        for (int it = 0; it < 4; it++) {
            int idx = it * 256 + tid;    // 0..1023 float4s
            int r = idx >> 3;            // 0..127
            int q = idx & 7;             // 0..7 (quad of 4 floats)
            int gr = rowbase + r; if (gr > nrows - 1) gr = nrows - 1;
            float4 v = *(const float4*)(As + (size_t)gr * DIM + kb + q * 4);
            uint32_t h0, l0, h1, l1;
            split2(v.x, v.y, h0, l0);
            split2(v.z, v.w, h1, l1);
            uint32_t* ph = (uint32_t*)&Ah[r * STR + q * 4];
            uint32_t* pl = (uint32_t*)&Al[r * STR + q * 4];
            ph[0] = h0; ph[1] = h1;
            pl[0] = l0; pl[1] = l1;
        }
        // ---- convert W chunk: 128 rows (j) x 32 cols ----
#pragma unroll
        for (int it = 0; it < 4; it++) {
            int idx = it * 256 + tid;
            int r = idx >> 3;
            int q = idx & 7;
            float4 v = *(const float4*)(W + (size_t)r * DIM + kb + q * 4);
            uint32_t h0, l0, h1, l1;
            split2(v.x, v.y, h0, l0);
            split2(v.z, v.w, h1, l1);
            uint32_t* ph = (uint32_t*)&Bh[r * STR + q * 4];
            uint32_t* pl = (uint32_t*)&Bl[r * STR + q * 4];
            ph[0] = h0; ph[1] = h1;
            pl[0] = l0; pl[1] = l1;
        }
        __syncthreads();

        // ---- MMA: 2 k-steps of 16 ----
#pragma unroll
        for (int ks = 0; ks < 2; ks++) {
            int k0 = ks * 16;

            uint32_t ahi[2][4], alo[2][4];
#pragma unroll
            for (int mt = 0; mt < 2; mt++) {
                uint32_t off = (uint32_t)((warp_m + mt * 16 + a_r) * STR + k0 + a_c) * 2;
                ldm4(ahi[mt], ah_base + off);
                ldm4(alo[mt], al_base + off);
            }

            // B in two halves of 32 cols (2 x4-loads per half)
#pragma unroll
            for (int h = 0; h < 2; h++) {
                uint32_t bhi[2][4], blo[2][4];
#pragma unroll
                for (int p = 0; p < 2; p++) {
                    int n0 = warp_n + h * 32 + p * 16;
                    uint32_t off = (uint32_t)((n0 + b_nofs) * STR + k0 + b_kofs) * 2;
                    ldm4(bhi[p], bh_base + off);
                    ldm4(blo[p], bl_base + off);
                }
#pragma unroll
                for (int mt = 0; mt < 2; mt++) {
#pragma unroll
                    for (int p = 0; p < 2; p++) {
#pragma unroll
                        for (int s = 0; s < 2; s++) {
                            int nt = h * 4 + p * 2 + s;
                            mma_bf16(acc[mt][nt], ahi[mt], bhi[p][s * 2], bhi[p][s * 2 + 1]); // hi*hi
                            mma_bf16(acc[mt][nt], ahi[mt], blo[p][s * 2], blo[p][s * 2 + 1]); // hi*lo
                            mma_bf16(acc[mt][nt], alo[mt], bhi[p][s * 2], bhi[p][s * 2 + 1]); // lo*hi
                        }
                    }
                }
            }
        }
    }

    // ---- epilogue: bias (+relu), float2 stores ----
    int c_r = lane >> 2;            // 0..7
    int c_c = (lane & 3) * 2;       // 0,2,4,6
#pragma unroll
    for (int mt = 0; mt < 2; mt++) {
        int r0 = rowbase + warp_m + mt * 16 + c_r;
        int r1 = r0 + 8;
#pragma unroll
        for (int nt = 0; nt < 8; nt++) {
            int c = warp_n + nt * 8 + c_c;
            float v0 = acc[mt][nt][0] + bs[c];
            float v1 = acc[mt][nt][1] + bs[c + 1];
            float v2 = acc[mt][nt][2] + bs[c];
            float v3 = acc[mt][nt][3] + bs[c + 1];
            if (do_relu) {
                v0 = fmaxf(v0, 0.f); v1 = fmaxf(v1, 0.f);
                v2 = fmaxf(v2, 0.f); v3 = fmaxf(v3, 0.f);
            }
            if (r0 < nrows) *(float2*)(out + (size_t)r0 * DIM + c) = make_float2(v0, v1);
            if (r1 < nrows) *(float2*)(out + (size_t)r1 * DIM + c) = make_float2(v2, v3);
        }
    }
}

// ---------------------------------------------------------------------------
extern "C" void kernel_launch(void* const* d_in, const int* in_sizes, int n_in,
                              void* d_out, int out_size)
{
    const float* x   = (const float*)d_in[0];
    const int*   src = (const int*)  d_in[1];
    const int*   dst = (const int*)  d_in[2];
    const float* wt  = (const float*)d_in[3];
    const float* Ws1 = (const float*)d_in[4];
    const float* Wn1 = (const float*)d_in[5];
    const float* b1  = (const float*)d_in[6];
    const float* Ws2 = (const float*)d_in[7];
    const float* Wn2 = (const float*)d_in[8];
    const float* b2  = (const float*)d_in[9];
    float* out = (float*)d_out;

    int E = in_sizes[1];

    int   *cnt, *row, *cur, *bsum, *bofs, *esrc;
    float *ew, *h1, *hn;
    cudaGetSymbolAddress((void**)&cnt,  g_cnt);
    cudaGetSymbolAddress((void**)&row,  g_row);
    cudaGetSymbolAddress((void**)&cur,  g_cur);
    cudaGetSymbolAddress((void**)&bsum, g_bsum);
    cudaGetSymbolAddress((void**)&bofs, g_bofs);
    cudaGetSymbolAddress((void**)&esrc, g_esrc);
    cudaGetSymbolAddress((void**)&ew,   g_ew);
    cudaGetSymbolAddress((void**)&h1,   g_h1);
    cudaGetSymbolAddress((void**)&hn,   g_hn);

    int eblocks  = (E + 255) / 256;
    int gblocks  = (N_NODES + MM_TILE - 1) / MM_TILE;   // 391
    int nwblocks = (N_NODES + 7) / 8;

    // ---- CSR build (by dst) ----
    zero_kernel<<<64, 256>>>((float4*)cnt, N_NODES / 4);
    hist_kernel<<<eblocks, 256>>>(dst, cnt, E);
    scan_bsum_kernel<<<SCAN_NB, SCAN_BLK>>>(cnt, bsum);
    scan_bofs_kernel<<<1, SCAN_BLK>>>(bsum, bofs, row);
    scan_write_kernel<<<SCAN_NB, SCAN_BLK>>>(cnt, bofs, row, cur);
    scatter_kernel<<<eblocks, 256>>>(src, dst, wt, cur, esrc, ew, E);

    // ---- layer 1 ----
    gather_kernel<<<nwblocks, 256>>>(x, row, esrc, ew, hn);
    sage_gemm_mma<<<gblocks, 256>>>(x, hn, Ws1, Wn1, b1, h1, N_NODES, 1);

    // ---- layer 2 ----
    gather_kernel<<<nwblocks, 256>>>(h1, row, esrc, ew, hn);
    sage_gemm_mma<<<gblocks, 256>>>(h1, hn, Ws2, Wn2, b2, out, N_NODES, 0);
}